// round 3
// baseline (speedup 1.0000x reference)
#include <cuda_runtime.h>
#include <cuda_bf16.h>
#include <cstdint>

// ---------------------------------------------------------------------------
// V0 = pt @ (U0 * s1)^T, V1 = pt @ (U1 * s0)^T;  s_i = colsum(U_i), K = 32.
// Tensor-core path via warp-level mma.sync (sm_103 base target: no tcgen05).
// fp32 -> bf16 hi/lo split, 3 terms (hh + lh + hl) accumulated in fp32:
//   A smem = [ah | al]  (K = 64 halves),  B smem = [bh | bl]
//   term pairs (a_kstep, b_kstep) of 16: (0,0)(1,1) (2,0)(3,1) (0,2)(1,3)
// Tile 128x128, 8 warps (4x2), warp tile 32x64, mma.m16n8k16.
// ---------------------------------------------------------------------------

#define R_DIM 32
#define BM 128
#define BN 128
#define LDT 72          // smem row stride in halves (144 B, 16B-aligned, conflict-free)

__device__ float g_s[2][R_DIM];   // g_s[0]=colsum(U0), g_s[1]=colsum(U1)

__device__ __forceinline__ uint32_t smem_u32(const void* p) {
    uint32_t a;
    asm("{ .reg .u64 t; cvta.to.shared.u64 t, %1; cvt.u32.u64 %0, t; }"
        : "=r"(a) : "l"(p));
    return a;
}

__device__ __forceinline__ void ldsm_x4(uint32_t addr, uint32_t r[4]) {
    asm volatile("ldmatrix.sync.aligned.m8n8.x4.shared.b16 {%0,%1,%2,%3}, [%4];"
                 : "=r"(r[0]), "=r"(r[1]), "=r"(r[2]), "=r"(r[3]) : "r"(addr));
}

__device__ __forceinline__ void mma_16816(float c[4], const uint32_t a[4],
                                          uint32_t b0, uint32_t b1) {
    asm volatile(
        "mma.sync.aligned.m16n8k16.row.col.f32.bf16.bf16.f32 "
        "{%0,%1,%2,%3}, {%4,%5,%6,%7}, {%8,%9}, {%0,%1,%2,%3};"
        : "+f"(c[0]), "+f"(c[1]), "+f"(c[2]), "+f"(c[3])
        : "r"(a[0]), "r"(a[1]), "r"(a[2]), "r"(a[3]), "r"(b0), "r"(b1));
}

// pack 4 fp32 -> (hi bf16x4, lo bf16x4)
__device__ __forceinline__ uint64_t split4(float4 v, uint64_t& lo_out) {
    __nv_bfloat16 h0 = __float2bfloat16(v.x), h1 = __float2bfloat16(v.y);
    __nv_bfloat16 h2 = __float2bfloat16(v.z), h3 = __float2bfloat16(v.w);
    __nv_bfloat16 l0 = __float2bfloat16(v.x - __bfloat162float(h0));
    __nv_bfloat16 l1 = __float2bfloat16(v.y - __bfloat162float(h1));
    __nv_bfloat16 l2 = __float2bfloat16(v.z - __bfloat162float(h2));
    __nv_bfloat16 l3 = __float2bfloat16(v.w - __bfloat162float(h3));
    union { __nv_bfloat16 h[4]; uint64_t u; } ph, pl;
    ph.h[0] = h0; ph.h[1] = h1; ph.h[2] = h2; ph.h[3] = h3;
    pl.h[0] = l0; pl.h[1] = l1; pl.h[2] = l2; pl.h[3] = l3;
    lo_out = pl.u;
    return ph.u;
}

// ---------------------------------------------------------------------------
// colsum: 2 blocks x 1024 threads, float4 loads, deterministic tree.
// ---------------------------------------------------------------------------
__global__ __launch_bounds__(1024)
void colsum_kernel(const float* __restrict__ U0, int n0,
                   const float* __restrict__ U1, int n1) {
    const float* U = (blockIdx.x == 0) ? U0 : U1;
    const int n    = (blockIdx.x == 0) ? n0 : n1;

    __shared__ float part[128][R_DIM];
    const int t = threadIdx.x;
    const int c4 = (t & 7) * 4;        // column quad
    const int grp = t >> 3;            // 0..127 row group

    float4 acc = make_float4(0.f, 0.f, 0.f, 0.f);
    for (int r = grp; r < n; r += 128) {
        float4 v = *(const float4*)(U + (size_t)r * R_DIM + c4);
        acc.x += v.x; acc.y += v.y; acc.z += v.z; acc.w += v.w;
    }
    part[grp][c4 + 0] = acc.x;
    part[grp][c4 + 1] = acc.y;
    part[grp][c4 + 2] = acc.z;
    part[grp][c4 + 3] = acc.w;
    __syncthreads();

    if (t < R_DIM) {
        float s = 0.0f;
        #pragma unroll 8
        for (int g = 0; g < 128; ++g) s += part[g][t];
        g_s[blockIdx.x][t] = s;
    }
}

// ---------------------------------------------------------------------------
// GEMM: C[P,N] = A[P,32] @ (B[N,32]*s)^T  via bf16 split mma.sync.
// ---------------------------------------------------------------------------
__global__ __launch_bounds__(256)
void mma_gemm_kernel(const float* __restrict__ A,
                     const float* __restrict__ B,
                     float* __restrict__ C,
                     int P, int N, int s_idx) {
    __shared__ __align__(16) __nv_bfloat16 sA[BM * LDT];   // 18432 B
    __shared__ __align__(16) __nv_bfloat16 sB[BN * LDT];   // 18432 B

    const uint32_t s_a = smem_u32(sA);
    const uint32_t s_b = smem_u32(sB);

    const int tid  = threadIdx.x;
    const int wid  = tid >> 5;
    const int lane = tid & 31;
    const int m0 = blockIdx.y * BM;
    const int n0 = blockIdx.x * BN;

    // ---- fill A tile: 128 rows x 8 quads, 4 quads/thread ----
    #pragma unroll
    for (int i = 0; i < 4; ++i) {
        int idx = i * 256 + tid;
        int r = idx >> 3, q = idx & 7;
        int row = m0 + r;
        float4 v = make_float4(0.f, 0.f, 0.f, 0.f);
        if (row < P) v = *(const float4*)(A + (size_t)row * R_DIM + q * 4);
        uint64_t lo, hi = split4(v, lo);
        uint32_t base = r * (LDT * 2) + q * 8;         // bytes
        asm volatile("st.shared.b64 [%0], %1;" :: "r"(s_a + base), "l"(hi) : "memory");
        asm volatile("st.shared.b64 [%0], %1;" :: "r"(s_a + base + 64), "l"(lo) : "memory");
    }

    // ---- fill B tile (scale fused before split) ----
    const float* sv = g_s[s_idx];
    #pragma unroll
    for (int i = 0; i < 4; ++i) {
        int idx = i * 256 + tid;
        int r = idx >> 3, q = idx & 7;
        int nn = n0 + r;
        float4 v = make_float4(0.f, 0.f, 0.f, 0.f);
        if (nn < N) {
            v = *(const float4*)(B + (size_t)nn * R_DIM + q * 4);
            v.x *= sv[q * 4 + 0]; v.y *= sv[q * 4 + 1];
            v.z *= sv[q * 4 + 2]; v.w *= sv[q * 4 + 3];
        }
        uint64_t lo, hi = split4(v, lo);
        uint32_t base = r * (LDT * 2) + q * 8;
        asm volatile("st.shared.b64 [%0], %1;" :: "r"(s_b + base), "l"(hi) : "memory");
        asm volatile("st.shared.b64 [%0], %1;" :: "r"(s_b + base + 64), "l"(lo) : "memory");
    }
    __syncthreads();

    // ---- warp tiles: 4 (m) x 2 (n) warps; warp covers 32x64 ----
    const int m_w = (wid >> 1) * 32;
    const int n_w = (wid & 1) * 64;

    float acc[2][8][4];
    #pragma unroll
    for (int fm = 0; fm < 2; ++fm)
        #pragma unroll
        for (int fn = 0; fn < 8; ++fn)
            #pragma unroll
            for (int j = 0; j < 4; ++j) acc[fm][fn][j] = 0.f;

    // A ldmatrix address (row-major m16k16): lanes 0-15 rows, 16-31 rows @k+8
    const uint32_t a_row = m_w + (lane & 15);
    const uint32_t a_koff = (lane >> 4) * 8;
    // B ldmatrix address ([n][k] row-major = col for mma): covers two n8 frags
    const uint32_t b_row = n_w + (lane >> 4) * 8 + (lane & 7);
    const uint32_t b_koff = ((lane >> 3) & 1) * 8;

    // term pairs (a_kstep, b_kstep), ksteps in units of 16 halves
    const int aks[6] = {0, 1, 2, 3, 0, 1};
    const int bks[6] = {0, 1, 0, 1, 2, 3};

    #pragma unroll
    for (int p = 0; p < 6; ++p) {
        uint32_t afrag[2][4];
        #pragma unroll
        for (int fm = 0; fm < 2; ++fm) {
            uint32_t addr = s_a + (a_row + fm * 16) * (LDT * 2)
                                + (aks[p] * 16 + a_koff) * 2;
            ldsm_x4(addr, afrag[fm]);
        }
        uint32_t bfrag[8][2];
        #pragma unroll
        for (int f2 = 0; f2 < 4; ++f2) {
            uint32_t r[4];
            uint32_t addr = s_b + (b_row + f2 * 16) * (LDT * 2)
                                + (bks[p] * 16 + b_koff) * 2;
            ldsm_x4(addr, r);
            bfrag[f2 * 2 + 0][0] = r[0]; bfrag[f2 * 2 + 0][1] = r[1];
            bfrag[f2 * 2 + 1][0] = r[2]; bfrag[f2 * 2 + 1][1] = r[3];
        }
        #pragma unroll
        for (int fm = 0; fm < 2; ++fm)
            #pragma unroll
            for (int fn = 0; fn < 8; ++fn)
                mma_16816(acc[fm][fn], afrag[fm], bfrag[fn][0], bfrag[fn][1]);
    }

    // ---- epilogue: direct float2 stores ----
    const int g  = lane >> 2;
    const int tg = lane & 3;
    #pragma unroll
    for (int fm = 0; fm < 2; ++fm) {
        #pragma unroll
        for (int fn = 0; fn < 8; ++fn) {
            int col = n0 + n_w + fn * 8 + tg * 2;
            if (col < N) {                           // N even -> pair valid
                int r0 = m0 + m_w + fm * 16 + g;
                int r1 = r0 + 8;
                if (r0 < P) {
                    float2 o = make_float2(acc[fm][fn][0], acc[fm][fn][1]);
                    *(float2*)(C + (size_t)r0 * N + col) = o;
                }
                if (r1 < P) {
                    float2 o = make_float2(acc[fm][fn][2], acc[fm][fn][3]);
                    *(float2*)(C + (size_t)r1 * N + col) = o;
                }
            }
        }
    }
}

// ---------------------------------------------------------------------------
extern "C" void kernel_launch(void* const* d_in, const int* in_sizes, int n_in,
                              void* d_out, int out_size) {
    const float* pt = (const float*)d_in[0];   // [P, 32]
    const float* U0 = (const float*)d_in[1];   // [N0, 32]
    const float* U1 = (const float*)d_in[2];   // [N1, 32]
    float* out = (float*)d_out;

    const int P  = in_sizes[0] / R_DIM;
    const int N0 = in_sizes[1] / R_DIM;
    const int N1 = in_sizes[2] / R_DIM;

    colsum_kernel<<<2, 1024>>>(U0, N0, U1, N1);

    dim3 g0((N0 + BN - 1) / BN, (P + BM - 1) / BM);
    mma_gemm_kernel<<<g0, 256>>>(pt, U0, out, P, N0, /*s1*/ 1);

    dim3 g1((N1 + BN - 1) / BN, (P + BM - 1) / BM);
    mma_gemm_kernel<<<g1, 256>>>(pt, U1, out + (size_t)P * N0, P, N1, /*s0*/ 0);
}

// round 5
// speedup vs baseline: 1.8230x; 1.8230x over previous
#include <cuda_runtime.h>
#include <cuda_fp16.h>
#include <cstdint>

// ---------------------------------------------------------------------------
// V0 = pt @ (U0 * s1)^T, V1 = pt @ (U1 * s0)^T;  s_i = colsum(U_i), K = 32.
// mma.sync fp16 path (sm_103 base target), asymmetric precision split:
//   A = ah + al (fp16 pair, residual ~2^-22),  B rounded to fp16 (~2^-12).
//   C = ah@bh + al@bh  -> elementwise rel err <= ~2^-11 (positive inputs).
// Fused single launch for both outputs.  Tile 128x64, warp tile 32x32.
// ---------------------------------------------------------------------------

#define R_DIM 32
#define BM 128
#define BN 64
#define LDA 72     // A smem row stride in halves (144 B): [ah 0..31 | al 32..63 | pad]
#define LDB 40     // B smem row stride in halves (80 B):  [bh 0..31 | pad]

__device__ float g_s[2][R_DIM];   // g_s[0]=colsum(U0), g_s[1]=colsum(U1)

__device__ __forceinline__ uint32_t smem_u32(const void* p) {
    uint32_t a;
    asm("{ .reg .u64 t; cvta.to.shared.u64 t, %1; cvt.u32.u64 %0, t; }"
        : "=r"(a) : "l"(p));
    return a;
}

__device__ __forceinline__ void ldsm_x4(uint32_t addr, uint32_t r[4]) {
    asm volatile("ldmatrix.sync.aligned.m8n8.x4.shared.b16 {%0,%1,%2,%3}, [%4];"
                 : "=r"(r[0]), "=r"(r[1]), "=r"(r[2]), "=r"(r[3]) : "r"(addr));
}

__device__ __forceinline__ void mma_16816(float c[4], const uint32_t a[4],
                                          uint32_t b0, uint32_t b1) {
    asm volatile(
        "mma.sync.aligned.m16n8k16.row.col.f32.f16.f16.f32 "
        "{%0,%1,%2,%3}, {%4,%5,%6,%7}, {%8,%9}, {%0,%1,%2,%3};"
        : "+f"(c[0]), "+f"(c[1]), "+f"(c[2]), "+f"(c[3])
        : "r"(a[0]), "r"(a[1]), "r"(a[2]), "r"(a[3]), "r"(b0), "r"(b1));
}

__device__ __forceinline__ void stg_cs_v2(float* p, float x, float y) {
    asm volatile("st.global.cs.v2.f32 [%0], {%1,%2};" :: "l"(p), "f"(x), "f"(y)
                 : "memory");
}

// 4 fp32 -> fp16 hi (packed u64) and fp16 residual lo (packed u64)
__device__ __forceinline__ uint64_t split4h(float4 v, uint64_t& lo_out) {
    __half h0 = __float2half_rn(v.x), h1 = __float2half_rn(v.y);
    __half h2 = __float2half_rn(v.z), h3 = __float2half_rn(v.w);
    __half l0 = __float2half_rn(v.x - __half2float(h0));
    __half l1 = __float2half_rn(v.y - __half2float(h1));
    __half l2 = __float2half_rn(v.z - __half2float(h2));
    __half l3 = __float2half_rn(v.w - __half2float(h3));
    union { __half h[4]; uint64_t u; } ph, pl;
    ph.h[0] = h0; ph.h[1] = h1; ph.h[2] = h2; ph.h[3] = h3;
    pl.h[0] = l0; pl.h[1] = l1; pl.h[2] = l2; pl.h[3] = l3;
    lo_out = pl.u;
    return ph.u;
}
// 4 fp32 -> fp16 rounded only
__device__ __forceinline__ uint64_t round4h(float4 v) {
    union { __half h[4]; uint64_t u; } p;
    p.h[0] = __float2half_rn(v.x); p.h[1] = __float2half_rn(v.y);
    p.h[2] = __float2half_rn(v.z); p.h[3] = __float2half_rn(v.w);
    return p.u;
}

// ---------------------------------------------------------------------------
// colsum: 2 blocks x 1024 threads, float4 loads, unrolled for MLP.
// ---------------------------------------------------------------------------
__global__ __launch_bounds__(1024)
void colsum_kernel(const float* __restrict__ U0, int n0,
                   const float* __restrict__ U1, int n1) {
    const float* U = (blockIdx.x == 0) ? U0 : U1;
    const int n    = (blockIdx.x == 0) ? n0 : n1;

    __shared__ float part[128][R_DIM];
    const int t = threadIdx.x;
    const int c4 = (t & 7) * 4;
    const int grp = t >> 3;            // 0..127

    float4 acc = make_float4(0.f, 0.f, 0.f, 0.f);
    #pragma unroll 4
    for (int r = grp; r < n; r += 128) {
        float4 v = *(const float4*)(U + (size_t)r * R_DIM + c4);
        acc.x += v.x; acc.y += v.y; acc.z += v.z; acc.w += v.w;
    }
    part[grp][c4 + 0] = acc.x;
    part[grp][c4 + 1] = acc.y;
    part[grp][c4 + 2] = acc.z;
    part[grp][c4 + 3] = acc.w;
    __syncthreads();

    if (t < R_DIM) {
        float s = 0.0f;
        #pragma unroll 16
        for (int g = 0; g < 128; ++g) s += part[g][t];
        g_s[blockIdx.x][t] = s;
    }
}

// ---------------------------------------------------------------------------
// Fused GEMM: both outputs in one launch.
// C0[P,N0] = A @ (U0*s1)^T at out, C1[P,N1] = A @ (U1*s0)^T at out+P*N0.
// ---------------------------------------------------------------------------
__global__ __launch_bounds__(256)
void mma_gemm_kernel(const float* __restrict__ A,
                     const float* __restrict__ B0,
                     const float* __restrict__ B1,
                     float* __restrict__ C_all,
                     int P, int N0, int N1, int T0, int NT0, int NT1) {
    __shared__ __align__(16) __half sA[BM * LDA];   // 18432 B
    __shared__ __align__(16) __half sB[BN * LDB];   //  5120 B

    const uint32_t s_a = smem_u32(sA);
    const uint32_t s_b = smem_u32(sB);

    // ---- decode flat block id -> (output, tile) ----
    int bid = blockIdx.x;
    const float* B;
    float* C;
    int N, s_idx, nt, mt;
    if (bid < T0) {
        B = B0; C = C_all; N = N0; s_idx = 1;
        nt = bid % NT0; mt = bid / NT0;
    } else {
        bid -= T0;
        B = B1; C = C_all + (size_t)P * N0; N = N1; s_idx = 0;
        nt = bid % NT1; mt = bid / NT1;
    }
    const int m0 = mt * BM;
    const int n0 = nt * BN;

    const int tid  = threadIdx.x;
    const int wid  = tid >> 5;
    const int lane = tid & 31;

    // ---- fill A tile: 128 rows x 8 quads, 4 quads/thread; split hi/lo ----
    #pragma unroll
    for (int i = 0; i < 4; ++i) {
        int idx = i * 256 + tid;
        int r = idx >> 3, q = idx & 7;
        int row = m0 + r;
        float4 v = make_float4(0.f, 0.f, 0.f, 0.f);
        if (row < P) v = *(const float4*)(A + (size_t)row * R_DIM + q * 4);
        uint64_t lo, hi = split4h(v, lo);
        uint32_t base = r * (LDA * 2) + q * 8;
        asm volatile("st.shared.b64 [%0], %1;" :: "r"(s_a + base), "l"(hi) : "memory");
        asm volatile("st.shared.b64 [%0], %1;" :: "r"(s_a + base + 64), "l"(lo) : "memory");
    }

    // ---- fill B tile: 64 rows x 8 quads, 2 quads/thread; scale, round ----
    const float* __restrict__ sv = g_s[s_idx];
    #pragma unroll
    for (int i = 0; i < 2; ++i) {
        int idx = i * 256 + tid;
        int r = idx >> 3, q = idx & 7;
        int nn = n0 + r;
        float4 v = make_float4(0.f, 0.f, 0.f, 0.f);
        if (nn < N) {
            v = *(const float4*)(B + (size_t)nn * R_DIM + q * 4);
            v.x *= sv[q * 4 + 0]; v.y *= sv[q * 4 + 1];
            v.z *= sv[q * 4 + 2]; v.w *= sv[q * 4 + 3];
        }
        uint64_t hb = round4h(v);
        uint32_t base = r * (LDB * 2) + q * 8;
        asm volatile("st.shared.b64 [%0], %1;" :: "r"(s_b + base), "l"(hb) : "memory");
    }
    __syncthreads();

    // ---- warp tiles: 4 (m) x 2 (n); warp covers 32x32 ----
    const int m_w = (wid >> 1) * 32;
    const int n_w = (wid & 1) * 32;

    float acc[2][4][4];
    #pragma unroll
    for (int fm = 0; fm < 2; ++fm)
        #pragma unroll
        for (int fn = 0; fn < 4; ++fn)
            #pragma unroll
            for (int j = 0; j < 4; ++j) acc[fm][fn][j] = 0.f;

    const uint32_t a_row  = m_w + (lane & 15);
    const uint32_t a_koff = (lane >> 4) * 8;
    const uint32_t b_row  = n_w + (lane >> 4) * 8 + (lane & 7);
    const uint32_t b_koff = ((lane >> 3) & 1) * 8;

    // products: (a_kstep, b_kstep) in k16 units: hh = (0,0)(1,1), lh = (2,0)(3,1)
    const int aks[4] = {0, 1, 2, 3};
    const int bks[4] = {0, 1, 0, 1};

    #pragma unroll
    for (int p = 0; p < 4; ++p) {
        uint32_t afrag[2][4];
        #pragma unroll
        for (int fm = 0; fm < 2; ++fm) {
            uint32_t addr = s_a + (a_row + fm * 16) * (LDA * 2)
                                + (aks[p] * 16 + a_koff) * 2;
            ldsm_x4(addr, afrag[fm]);
        }
        uint32_t bfrag[4][2];
        #pragma unroll
        for (int f2 = 0; f2 < 2; ++f2) {
            uint32_t r[4];
            uint32_t addr = s_b + (b_row + f2 * 16) * (LDB * 2)
                                + (bks[p] * 16 + b_koff) * 2;
            ldsm_x4(addr, r);
            bfrag[f2 * 2 + 0][0] = r[0]; bfrag[f2 * 2 + 0][1] = r[1];
            bfrag[f2 * 2 + 1][0] = r[2]; bfrag[f2 * 2 + 1][1] = r[3];
        }
        #pragma unroll
        for (int fm = 0; fm < 2; ++fm)
            #pragma unroll
            for (int fn = 0; fn < 4; ++fn)
                mma_16816(acc[fm][fn], afrag[fm], bfrag[fn][0], bfrag[fn][1]);
    }

    // ---- epilogue: streaming float2 stores ----
    const int g  = lane >> 2;
    const int tg = lane & 3;
    #pragma unroll
    for (int fm = 0; fm < 2; ++fm) {
        #pragma unroll
        for (int fn = 0; fn < 4; ++fn) {
            int col = n0 + n_w + fn * 8 + tg * 2;
            if (col < N) {                           // N even -> pair valid
                int r0 = m0 + m_w + fm * 16 + g;
                int r1 = r0 + 8;
                if (r0 < P) stg_cs_v2(C + (size_t)r0 * N + col,
                                      acc[fm][fn][0], acc[fm][fn][1]);
                if (r1 < P) stg_cs_v2(C + (size_t)r1 * N + col,
                                      acc[fm][fn][2], acc[fm][fn][3]);
            }
        }
    }
}

// ---------------------------------------------------------------------------
extern "C" void kernel_launch(void* const* d_in, const int* in_sizes, int n_in,
                              void* d_out, int out_size) {
    const float* pt = (const float*)d_in[0];   // [P, 32]
    const float* U0 = (const float*)d_in[1];   // [N0, 32]
    const float* U1 = (const float*)d_in[2];   // [N1, 32]
    float* out = (float*)d_out;

    const int P  = in_sizes[0] / R_DIM;
    const int N0 = in_sizes[1] / R_DIM;
    const int N1 = in_sizes[2] / R_DIM;

    colsum_kernel<<<2, 1024>>>(U0, N0, U1, N1);

    const int MT  = (P + BM - 1) / BM;
    const int NT0 = (N0 + BN - 1) / BN;
    const int NT1 = (N1 + BN - 1) / BN;
    const int T0  = MT * NT0;
    const int T1  = MT * NT1;

    mma_gemm_kernel<<<T0 + T1, 256>>>(pt, U0, U1, out, P, N0, N1, T0, NT0, NT1);
}